// round 16
// baseline (speedup 1.0000x reference)
#include <cuda_runtime.h>
#include <cstdint>
#include <math.h>

// TsCv: sliding-window coefficient of variation.
// x: (64, 256, 4096) fp32  -> out: (64, 256, 816) fp32
// window = 20, stride = 5, var ddof=1, cv = std/(mean+1e-8), NaN -> 0.
//
// Numerics: ONLY the window SUM must bit-match the reference (XLA:GPU
// warp-shuffle tree, shfl_down 16,8,4,2,1 with zero lanes 20..31).
// Downstream math needs only relative accuracy (threshold 1e-3; measured
// margin ~4e-8): chunked sumsq identity + approx sqrt/div.
//
// Perf history: R10 cp.async 2-stage -> 5.9TB/s; R12 WPT=3 -> 53.6us;
// R14 WPT=4 + LDS.128 + chunked sumsq -> 53.2us, DRAM 79.2%.
// This version: PERSISTENT grid-stride CTAs (592 = 4/SM x 148) with a
// 3-stage cp.async ring (48KB smem) -> two rows in flight per CTA at all
// times, pipeline fills once per CTA lifetime, no wave transitions.

#define SEQ_LEN   4096
#define MIN_W     20
#define STRIDE_W  5
#define OUT_LEN   ((SEQ_LEN - MIN_W) / STRIDE_W + 1)   // 816
#define EPS_CV    1e-8f
#define WPT       4
#define N_WORK    (OUT_LEN / WPT)                      // 204 compute threads
#define BLOCK_T   224                                  // 7 warps
#define SPAN_V4   9                                    // 36 words loaded
#define N_CHUNK   7                                    // chunks of 5 in span
#define N_STAGES  3
#define VEC_PER_ROW  (SEQ_LEN / 4)                     // 1024 float4
#define GRID_CTAS 592                                  // 4 per SM x 148

__device__ __forceinline__ float warp_tree_sum20(const float* __restrict__ w)
{
    float A0 = __fadd_rn(__fadd_rn(__fadd_rn(w[0], w[16]), w[8]),
                         __fadd_rn(w[4], w[12]));
    float A1 = __fadd_rn(__fadd_rn(__fadd_rn(w[1], w[17]), w[9]),
                         __fadd_rn(w[5], w[13]));
    float A2 = __fadd_rn(__fadd_rn(__fadd_rn(w[2], w[18]), w[10]),
                         __fadd_rn(w[6], w[14]));
    float A3 = __fadd_rn(__fadd_rn(__fadd_rn(w[3], w[19]), w[11]),
                         __fadd_rn(w[7], w[15]));
    return __fadd_rn(__fadd_rn(A0, A2), __fadd_rn(A1, A3));
}

__global__ __launch_bounds__(BLOCK_T, 4)
void TsCv_29257317220818_kernel(const float* __restrict__ x,
                                float* __restrict__ out,
                                int n_rows)
{
    __shared__ float4 buf[N_STAGES][VEC_PER_ROW];   // 3 x 16 KB

    const int tid = threadIdx.x;

    // Prefetch one full row into a stage; ALWAYS commits a group so the
    // wait_group counting stays uniform across CTAs/iterations.
    auto prefetch = [&](int r, int stage) {
        if (r < n_rows) {
            const float4* __restrict__ src4 =
                (const float4*)(x + (size_t)r * SEQ_LEN);
            float4* dstb = buf[stage];
            for (int k = tid; k < VEC_PER_ROW; k += BLOCK_T) {
                unsigned int saddr =
                    (unsigned int)__cvta_generic_to_shared(&dstb[k]);
                asm volatile("cp.async.cg.shared.global [%0], [%1], 16;\n"
                             :: "r"(saddr), "l"(&src4[k]));
            }
        }
        asm volatile("cp.async.commit_group;\n");
    };

    // Fill the pipeline: rows r0, r0+step into stages 0, 1.
    const int step = gridDim.x;
    prefetch(blockIdx.x, 0);
    prefetch(blockIdx.x + step, 1);

    int idx = 0;
    for (int r = blockIdx.x; r < n_rows; r += step, idx++) {
        // Keep two rows ahead in flight.
        prefetch(r + 2 * step, (idx + 2) % N_STAGES);

        // Wait until only the two newest groups are pending -> row r landed.
        asm volatile("cp.async.wait_group 2;\n");
        __syncthreads();

        if (tid < N_WORK) {
            const float4* __restrict__ rowv = buf[idx % N_STAGES];
            // thread t -> windows [4t, 4t+4), span words [20t, 20t+35).
            const int o0 = tid * WPT;                     // 0..812
            const int v0 = tid * (WPT * STRIDE_W) / 4;    // 5t, float4 index

            float w[SPAN_V4 * 4];                         // 36 floats
            #pragma unroll
            for (int k = 0; k < SPAN_V4; k++) {
                float4 v = rowv[v0 + k];                  // LDS.128, no conflicts
                w[4 * k + 0] = v.x;
                w[4 * k + 1] = v.y;
                w[4 * k + 2] = v.z;
                w[4 * k + 3] = v.w;
            }

            // Chunked sum-of-squares: S[c] = sum_{i<5} w[5c+i]^2
            float S[N_CHUNK];
            #pragma unroll
            for (int c = 0; c < N_CHUNK; c++) {
                float s = __fmul_rn(w[5 * c], w[5 * c]);
                #pragma unroll
                for (int q = 1; q < STRIDE_W; q++)
                    s = fmaf(w[5 * c + q], w[5 * c + q], s);
                S[c] = s;
            }

            float4 res;
            float* resp = (float*)&res;
            #pragma unroll
            for (int j = 0; j < WPT; j++) {
                const float* ww = w + j * STRIDE_W;

                // Bit-exact reference sum (warp-shuffle tree order).
                const float sum  = warp_tree_sum20(ww);
                const float mean = sum * 0.05f;

                const float sumsq = __fadd_rn(__fadd_rn(S[j], S[j + 1]),
                                              __fadd_rn(S[j + 2], S[j + 3]));
                const float ssd = fmaf(-sum, mean, sumsq);
                float var = ssd * (1.0f / (MIN_W - 1));
                var = fmaxf(var, 0.0f);

                float sd;
                asm("sqrt.approx.f32 %0, %1;" : "=f"(sd) : "f"(var));
                const float den = mean + EPS_CV;
                float cv = __fdividef(sd, den);
                if (isnan(cv)) cv = 0.0f;
                resp[j] = cv;
            }

            // One 16B store: row base 3264B and o0=4t are both 16B-aligned.
            *(float4*)(out + (size_t)r * OUT_LEN + o0) = res;
        }
        __syncthreads();   // compute on this stage done before it is refilled
    }
}

extern "C" void kernel_launch(void* const* d_in, const int* in_sizes, int n_in,
                              void* d_out, int out_size)
{
    const float* x = (const float*)d_in[0];
    float* out = (float*)d_out;

    const int n_rows = in_sizes[0] / SEQ_LEN;   // 64 * 256 = 16384
    TsCv_29257317220818_kernel<<<GRID_CTAS, BLOCK_T>>>(x, out, n_rows);
}

// round 17
// speedup vs baseline: 1.0006x; 1.0006x over previous
#include <cuda_runtime.h>
#include <cstdint>
#include <math.h>

// TsCv: sliding-window coefficient of variation.
// x: (64, 256, 4096) fp32  -> out: (64, 256, 816) fp32
// window = 20, stride = 5, var ddof=1, cv = std/(mean+1e-8), NaN -> 0.
//
// Numerics: ONLY the window SUM must bit-match the reference (XLA:GPU
// warp-shuffle tree, shfl_down 16,8,4,2,1 with zero lanes 20..31).
// Downstream math needs only relative accuracy (threshold 1e-3; measured
// margin ~4e-8): chunked sumsq identity + approx sqrt/div.
//
// Perf history: R14 (2-stage cp.async, 8 rows/CTA, WPT=4, LDS.128, chunked
// sumsq) = 53.2us @ DRAM 79.2%, occ 50% (5 CTAs/SM). R15 persistent 3-stage
// at 4 CTAs/SM REGRESSED (72.6% DRAM): resident-CTA count beats per-CTA
// pipeline depth. This version: R14 verbatim with __launch_bounds__(224, 6)
// -> 6 CTAs/SM (33KB smem x 6 = 198KB fits 228KB carveout; reg cap 48 =
// what R14 already used). +20% outstanding row-streams per SM.

#define SEQ_LEN   4096
#define MIN_W     20
#define STRIDE_W  5
#define OUT_LEN   ((SEQ_LEN - MIN_W) / STRIDE_W + 1)   // 816
#define EPS_CV    1e-8f
#define WPT       4
#define N_WORK    (OUT_LEN / WPT)                      // 204 compute threads
#define BLOCK_T   224                                  // 7 warps
#define SPAN_W    (MIN_W + (WPT - 1) * STRIDE_W)       // 35 words
#define SPAN_V4   9                                    // 36 words loaded
#define N_CHUNK   (SPAN_W / STRIDE_W)                  // 7 chunks of 5
#define ROWS_PER_CTA 8
#define VEC_PER_ROW  (SEQ_LEN / 4)                     // 1024 float4

__device__ __forceinline__ float warp_tree_sum20(const float* __restrict__ w)
{
    float A0 = __fadd_rn(__fadd_rn(__fadd_rn(w[0], w[16]), w[8]),
                         __fadd_rn(w[4], w[12]));
    float A1 = __fadd_rn(__fadd_rn(__fadd_rn(w[1], w[17]), w[9]),
                         __fadd_rn(w[5], w[13]));
    float A2 = __fadd_rn(__fadd_rn(__fadd_rn(w[2], w[18]), w[10]),
                         __fadd_rn(w[6], w[14]));
    float A3 = __fadd_rn(__fadd_rn(__fadd_rn(w[3], w[19]), w[11]),
                         __fadd_rn(w[7], w[15]));
    return __fadd_rn(__fadd_rn(A0, A2), __fadd_rn(A1, A3));
}

__global__ __launch_bounds__(BLOCK_T, 6)
void TsCv_29257317220818_kernel(const float* __restrict__ x,
                                float* __restrict__ out,
                                int n_rows)
{
    __shared__ float4 buf[2][VEC_PER_ROW];   // 2 x 16 KB

    const int tid  = threadIdx.x;
    const int row0 = blockIdx.x * ROWS_PER_CTA;

    // cp.async prefetch of one full row, one commit group (all 224 threads).
    auto prefetch = [&](int i) {
        const int r = row0 + i;
        if (r < n_rows) {
            const float4* __restrict__ src4 =
                (const float4*)(x + (size_t)r * SEQ_LEN);
            float4* dstb = buf[i & 1];
            for (int k = tid; k < VEC_PER_ROW; k += BLOCK_T) {
                unsigned int saddr =
                    (unsigned int)__cvta_generic_to_shared(&dstb[k]);
                asm volatile("cp.async.cg.shared.global [%0], [%1], 16;\n"
                             :: "r"(saddr), "l"(&src4[k]));
            }
        }
        asm volatile("cp.async.commit_group;\n");
    };

    prefetch(0);

    for (int i = 0; i < ROWS_PER_CTA; i++) {
        const int r = row0 + i;

        if (i + 1 < ROWS_PER_CTA) {
            prefetch(i + 1);                              // overlap next row
            asm volatile("cp.async.wait_group 1;\n");     // current row ready
        } else {
            asm volatile("cp.async.wait_group 0;\n");
        }
        __syncthreads();

        if (r < n_rows && tid < N_WORK) {
            const float4* __restrict__ rowv = buf[i & 1];
            // thread t -> windows [4t, 4t+4), span words [20t, 20t+35).
            const int o0 = tid * WPT;                     // 0..812
            const int v0 = tid * (WPT * STRIDE_W) / 4;    // 5t, float4 index

            float w[SPAN_V4 * 4];                         // 36 floats
            #pragma unroll
            for (int k = 0; k < SPAN_V4; k++) {
                float4 v = rowv[v0 + k];                  // LDS.128, no conflicts
                w[4 * k + 0] = v.x;
                w[4 * k + 1] = v.y;
                w[4 * k + 2] = v.z;
                w[4 * k + 3] = v.w;
            }

            // Chunked sum-of-squares: S[c] = sum_{i<5} w[5c+i]^2
            float S[N_CHUNK];
            #pragma unroll
            for (int c = 0; c < N_CHUNK; c++) {
                float s = __fmul_rn(w[5 * c], w[5 * c]);
                #pragma unroll
                for (int q = 1; q < STRIDE_W; q++)
                    s = fmaf(w[5 * c + q], w[5 * c + q], s);
                S[c] = s;
            }

            float4 res;
            float* resp = (float*)&res;
            #pragma unroll
            for (int j = 0; j < WPT; j++) {
                const float* ww = w + j * STRIDE_W;

                // Bit-exact reference sum (warp-shuffle tree order).
                const float sum  = warp_tree_sum20(ww);
                const float mean = sum * 0.05f;

                const float sumsq = __fadd_rn(__fadd_rn(S[j], S[j + 1]),
                                              __fadd_rn(S[j + 2], S[j + 3]));
                const float ssd = fmaf(-sum, mean, sumsq);
                float var = ssd * (1.0f / (MIN_W - 1));
                var = fmaxf(var, 0.0f);

                float sd;
                asm("sqrt.approx.f32 %0, %1;" : "=f"(sd) : "f"(var));
                const float den = mean + EPS_CV;
                float cv = __fdividef(sd, den);
                if (isnan(cv)) cv = 0.0f;
                resp[j] = cv;
            }

            // One 16B store: row base 3264B and o0=4t are both 16B-aligned.
            *(float4*)(out + (size_t)r * OUT_LEN + o0) = res;
        }
        __syncthreads();   // all compute on buf[i&1] done before it's refilled
    }
}

extern "C" void kernel_launch(void* const* d_in, const int* in_sizes, int n_in,
                              void* d_out, int out_size)
{
    const float* x = (const float*)d_in[0];
    float* out = (float*)d_out;

    const int n_rows = in_sizes[0] / SEQ_LEN;   // 64 * 256 = 16384
    const int grid = (n_rows + ROWS_PER_CTA - 1) / ROWS_PER_CTA;  // 2048
    TsCv_29257317220818_kernel<<<grid, BLOCK_T>>>(x, out, n_rows);
}